// round 8
// baseline (speedup 1.0000x reference)
#include <cuda_runtime.h>
#include <cuda_bf16.h>
#include <cstdint>

// ChamferLoss: B=128, N=M=1024, 3D points (float4, channel 0 unused).
// Single-pass: each distance is computed ONCE and feeds BOTH min directions
// (row-min in registers, col-min via __reduce_min_sync using the
// positive-float-bits-as-int ordering trick). 268M -> 134M pair evals.
// dist_sq+1 computed as (pn + (qn+1)) - 2*dot via packed f32x2.

#define BATCHES   128
#define NPTS      1024
#define THREADS   128
#define ROWCHUNKS (NPTS / THREADS)   // 8 blocks per batch
#define NGROUPS   (NPTS / 2)         // 512 packed column pairs

__device__ int g_colmin[BATCHES * NPTS];   // per (batch, q-col) min bits

__device__ __forceinline__ unsigned long long pack2(float a, float b) {
    unsigned long long r;
    asm("mov.b64 %0, {%1, %2};" : "=l"(r) : "f"(a), "f"(b));
    return r;
}
__device__ __forceinline__ void unpack2(unsigned long long v, float& a, float& b) {
    asm("mov.b64 {%0, %1}, %2;" : "=f"(a), "=f"(b) : "l"(v));
}
__device__ __forceinline__ unsigned long long add2(unsigned long long a, unsigned long long b) {
    unsigned long long d;
    asm("add.rn.f32x2 %0, %1, %2;" : "=l"(d) : "l"(a), "l"(b));
    return d;
}
__device__ __forceinline__ unsigned long long fma2(unsigned long long a, unsigned long long b,
                                                   unsigned long long c) {
    unsigned long long d;
    asm("fma.rn.f32x2 %0, %1, %2, %3;" : "=l"(d) : "l"(a), "l"(b), "l"(c));
    return d;
}

__global__ void chamfer_init_kernel(float* out) {
    int idx = blockIdx.x * blockDim.x + threadIdx.x;
    if (idx < BATCHES * NPTS) g_colmin[idx] = 0x7F800000;  // +inf bits
    if (idx == 0) out[0] = 0.0f;
}

__global__ void __launch_bounds__(THREADS)
chamfer_main_kernel(const float4* __restrict__ p, const float4* __restrict__ q,
                    float* __restrict__ out) {
    // Packed column data: group j = q-points (2j, 2j+1):
    //   sq[4j+0]=(y0,y1) sq[4j+1]=(z0,z1) sq[4j+2]=(w0,w1) sq[4j+3]=(qn0+1,qn1+1)
    __shared__ unsigned long long sq[(NGROUPS + 1) * 4];
    __shared__ int colmin_w[4 * NPTS];     // per-warp col-min bits
    __shared__ float warp_sums[4];

    const int bid   = blockIdx.x;
    const int chunk = bid & (ROWCHUNKS - 1);
    const int b     = bid >> 3;
    const int tid   = threadIdx.x;
    const int wid   = tid >> 5;
    const int lid   = tid & 31;

    const float4* rowpts = p + b * NPTS;
    const float4* colpts = q + b * NPTS;

    // ---- Fill packed column smem (qn pre-biased by +1) ----
    #pragma unroll
    for (int i = tid; i < NGROUPS; i += THREADS) {
        float4 P0 = colpts[2 * i];
        float4 P1 = colpts[2 * i + 1];
        float n0 = P0.y * P0.y + P0.z * P0.z + P0.w * P0.w + 1.0f;
        float n1 = P1.y * P1.y + P1.z * P1.z + P1.w * P1.w + 1.0f;
        sq[4 * i + 0] = pack2(P0.y, P1.y);
        sq[4 * i + 1] = pack2(P0.z, P1.z);
        sq[4 * i + 2] = pack2(P0.w, P1.w);
        sq[4 * i + 3] = pack2(n0, n1);
    }
    if (tid < 4) sq[4 * NGROUPS + tid] = 0;   // prefetch padding

    // ---- This thread's p-row, coords pre-scaled by -2 ----
    const int r = chunk * THREADS + tid;
    float4 RP = rowpts[r];
    const float pn = RP.y * RP.y + RP.z * RP.z + RP.w * RP.w;
    const unsigned long long cx = pack2(-2.0f * RP.y, -2.0f * RP.y);
    const unsigned long long cy = pack2(-2.0f * RP.z, -2.0f * RP.z);
    const unsigned long long cz = pack2(-2.0f * RP.w, -2.0f * RP.w);
    const unsigned long long pn2 = pack2(pn, pn);

    __syncthreads();

    float rma = 3.4e38f, rmb = 3.4e38f;   // row-min partials (even/odd cols)

    const ulonglong2* sq2 = (const ulonglong2*)sq;
    int* cw = colmin_w + wid * NPTS;

    ulonglong2 u01 = sq2[0];
    ulonglong2 u23 = sq2[1];

    #pragma unroll 8
    for (int j = 0; j < NGROUPS; j++) {
        ulonglong2 n01 = sq2[2 * (j + 1)];
        ulonglong2 n23 = sq2[2 * (j + 1) + 1];

        // s = (pn + qn + 1) - 2*dot  -> strictly positive: int-ordered bits
        unsigned long long s = add2(u23.y, pn2);
        s = fma2(cx, u01.x, s);
        s = fma2(cy, u01.y, s);
        s = fma2(cz, u23.x, s);
        float t0, t1;
        unpack2(s, t0, t1);

        rma = fminf(rma, t0);              // row-min (per-lane, register)
        rmb = fminf(rmb, t1);

        int c0 = __reduce_min_sync(0xFFFFFFFFu, __float_as_int(t0));
        int c1 = __reduce_min_sync(0xFFFFFFFFu, __float_as_int(t1));
        if (lid == 0) *(int2*)&cw[2 * j] = make_int2(c0, c1);

        u01 = n01;
        u23 = n23;
    }

    __syncthreads();

    // ---- Col-min: combine 4 warps, push to global scratch ----
    #pragma unroll
    for (int c = tid; c < NPTS; c += THREADS) {
        int m = min(min(colmin_w[c],            colmin_w[NPTS + c]),
                    min(colmin_w[2 * NPTS + c], colmin_w[3 * NPTS + c]));
        atomicMin(&g_colmin[b * NPTS + c], m);
    }

    // ---- Row-min: final within block -> sqrt -> sum ----
    float ds = fminf(rma, rmb) - 1.0f;     // undo bias
    float local = sqrtf(fmaxf(ds, 0.0f) + 1e-16f);

    #pragma unroll
    for (int off = 16; off > 0; off >>= 1)
        local += __shfl_xor_sync(0xFFFFFFFFu, local, off);
    if (lid == 0) warp_sums[wid] = local;
    __syncthreads();
    if (tid == 0) {
        float sum = warp_sums[0] + warp_sums[1] + warp_sums[2] + warp_sums[3];
        atomicAdd(out, 0.5f * sum);
    }
}

__global__ void __launch_bounds__(256)
chamfer_final_kernel(float* __restrict__ out) {
    __shared__ float wsums[8];
    int idx = blockIdx.x * 256 + threadIdx.x;
    float v = __int_as_float(g_colmin[idx]);
    float local = sqrtf(fmaxf(v - 1.0f, 0.0f) + 1e-16f);

    #pragma unroll
    for (int off = 16; off > 0; off >>= 1)
        local += __shfl_xor_sync(0xFFFFFFFFu, local, off);
    int wid = threadIdx.x >> 5, lid = threadIdx.x & 31;
    if (lid == 0) wsums[wid] = local;
    __syncthreads();
    if (wid == 0) {
        float s = (lid < 8) ? wsums[lid] : 0.0f;
        #pragma unroll
        for (int off = 4; off > 0; off >>= 1)
            s += __shfl_xor_sync(0xFFFFFFFFu, s, off);
        if (lid == 0) atomicAdd(out, 0.5f * s);
    }
}

extern "C" void kernel_launch(void* const* d_in, const int* in_sizes, int n_in,
                              void* d_out, int out_size) {
    const float4* p = (const float4*)d_in[0];
    const float4* q = (const float4*)d_in[1];
    float* out = (float*)d_out;

    chamfer_init_kernel<<<(BATCHES * NPTS + 255) / 256, 256>>>(out);
    chamfer_main_kernel<<<BATCHES * ROWCHUNKS, THREADS>>>(p, q, out);
    chamfer_final_kernel<<<(BATCHES * NPTS) / 256, 256>>>(out);
}

// round 9
// speedup vs baseline: 1.1856x; 1.1856x over previous
#include <cuda_runtime.h>
#include <cuda_bf16.h>
#include <cstdint>

// ChamferLoss: B=128, N=M=1024, 3D points (float4, channel 0 unused).
// Single-pass with RPT=2: each distance computed ONCE feeds BOTH directions.
// Row-min in registers; col-min = per-lane min over its 2 rows, then one
// redux.sync.min.s32 per column (positive float bits are int-ordered).
// Col partials stored per (block,chunk) with plain STG -- no global atomics,
// no big init kernel. dist_sq+1 = (pn + (qn+1)) - 2*dot via packed f32x2.

#define BATCHES   128
#define NPTS      1024
#define THREADS   128
#define RPT       2
#define ROWS_PER_BLOCK (THREADS * RPT)        // 256
#define CHUNKS    (NPTS / ROWS_PER_BLOCK)     // 4
#define NGROUPS   (NPTS / 2)                  // 512 packed column pairs
#define MAINGRID  (BATCHES * CHUNKS)          // 512

__device__ int g_colmin_part[MAINGRID * NPTS];   // [b*CHUNKS+chunk][col] bits

__device__ __forceinline__ unsigned long long pack2(float a, float b) {
    unsigned long long r;
    asm("mov.b64 %0, {%1, %2};" : "=l"(r) : "f"(a), "f"(b));
    return r;
}
__device__ __forceinline__ void unpack2(unsigned long long v, float& a, float& b) {
    asm("mov.b64 {%0, %1}, %2;" : "=f"(a), "=f"(b) : "l"(v));
}
__device__ __forceinline__ unsigned long long add2(unsigned long long a, unsigned long long b) {
    unsigned long long d;
    asm("add.rn.f32x2 %0, %1, %2;" : "=l"(d) : "l"(a), "l"(b));
    return d;
}
__device__ __forceinline__ unsigned long long fma2(unsigned long long a, unsigned long long b,
                                                   unsigned long long c) {
    unsigned long long d;
    asm("fma.rn.f32x2 %0, %1, %2, %3;" : "=l"(d) : "l"(a), "l"(b), "l"(c));
    return d;
}

__global__ void chamfer_zero_kernel(float* out) {
    out[0] = 0.0f;
}

__global__ void __launch_bounds__(THREADS)
chamfer_main_kernel(const float4* __restrict__ p, const float4* __restrict__ q,
                    float* __restrict__ out) {
    // Packed column data: group j = q-points (2j, 2j+1):
    //   sq[4j+0]=(y0,y1) sq[4j+1]=(z0,z1) sq[4j+2]=(w0,w1) sq[4j+3]=(qn0+1,qn1+1)
    __shared__ unsigned long long sq[(NGROUPS + 1) * 4];
    __shared__ int colmin_w[4 * NPTS];     // per-warp col-min bits
    __shared__ float warp_sums[4];

    const int bid   = blockIdx.x;
    const int chunk = bid & (CHUNKS - 1);
    const int b     = bid >> 2;
    const int tid   = threadIdx.x;
    const int wid   = tid >> 5;
    const int lid   = tid & 31;

    const float4* rowpts = p + b * NPTS;
    const float4* colpts = q + b * NPTS;

    // ---- Fill packed column smem (qn pre-biased by +1) ----
    #pragma unroll
    for (int i = tid; i < NGROUPS; i += THREADS) {
        float4 P0 = colpts[2 * i];
        float4 P1 = colpts[2 * i + 1];
        float n0 = P0.y * P0.y + P0.z * P0.z + P0.w * P0.w + 1.0f;
        float n1 = P1.y * P1.y + P1.z * P1.z + P1.w * P1.w + 1.0f;
        sq[4 * i + 0] = pack2(P0.y, P1.y);
        sq[4 * i + 1] = pack2(P0.z, P1.z);
        sq[4 * i + 2] = pack2(P0.w, P1.w);
        sq[4 * i + 3] = pack2(n0, n1);
    }
    if (tid < 4) sq[4 * NGROUPS + tid] = 0;   // prefetch padding

    // ---- This thread's 2 p-rows, coords pre-scaled by -2, pn pre-packed ----
    unsigned long long cx[RPT], cy[RPT], cz[RPT], pn2[RPT];
    float pn[RPT];
    #pragma unroll
    for (int k = 0; k < RPT; k++) {
        int r = chunk * ROWS_PER_BLOCK + k * THREADS + tid;
        float4 RP = rowpts[r];
        pn[k] = RP.y * RP.y + RP.z * RP.z + RP.w * RP.w;
        cx[k] = pack2(-2.0f * RP.y, -2.0f * RP.y);
        cy[k] = pack2(-2.0f * RP.z, -2.0f * RP.z);
        cz[k] = pack2(-2.0f * RP.w, -2.0f * RP.w);
        pn2[k] = pack2(pn[k], pn[k]);
    }

    __syncthreads();

    float rma[RPT], rmb[RPT];
    #pragma unroll
    for (int k = 0; k < RPT; k++) { rma[k] = 3.4e38f; rmb[k] = 3.4e38f; }

    const ulonglong2* sq2 = (const ulonglong2*)sq;
    int* cw = colmin_w + wid * NPTS;

    ulonglong2 u01 = sq2[0];
    ulonglong2 u23 = sq2[1];

    #pragma unroll 8
    for (int j = 0; j < NGROUPS; j++) {
        ulonglong2 n01 = sq2[2 * (j + 1)];
        ulonglong2 n23 = sq2[2 * (j + 1) + 1];

        float t0[RPT], t1[RPT];
        #pragma unroll
        for (int k = 0; k < RPT; k++) {
            // s = (pn + qn + 1) - 2*dot  -> strictly positive
            unsigned long long s = add2(u23.y, pn2[k]);
            s = fma2(cx[k], u01.x, s);
            s = fma2(cy[k], u01.y, s);
            s = fma2(cz[k], u23.x, s);
            unpack2(s, t0[k], t1[k]);
            rma[k] = fminf(rma[k], t0[k]);     // row-min partials
            rmb[k] = fminf(rmb[k], t1[k]);
        }

        // col-min: min over this lane's 2 rows, then across 32 lanes (64 rows)
        float c0f = fminf(t0[0], t0[1]);
        float c1f = fminf(t1[0], t1[1]);
        int c0 = __reduce_min_sync(0xFFFFFFFFu, __float_as_int(c0f));
        int c1 = __reduce_min_sync(0xFFFFFFFFu, __float_as_int(c1f));
        if (lid == 0) *(int2*)&cw[2 * j] = make_int2(c0, c1);

        u01 = n01;
        u23 = n23;
    }

    __syncthreads();

    // ---- Col-min: combine 4 warps, plain store to per-block partials ----
    #pragma unroll
    for (int c = tid; c < NPTS; c += THREADS) {
        int m = min(min(colmin_w[c],            colmin_w[NPTS + c]),
                    min(colmin_w[2 * NPTS + c], colmin_w[3 * NPTS + c]));
        g_colmin_part[bid * NPTS + c] = m;
    }

    // ---- Row-min: final within thread -> sqrt -> block sum ----
    float local = 0.0f;
    #pragma unroll
    for (int k = 0; k < RPT; k++) {
        float ds = fminf(rma[k], rmb[k]) - 1.0f;   // undo bias
        local += sqrtf(fmaxf(ds, 0.0f) + 1e-16f);
    }

    #pragma unroll
    for (int off = 16; off > 0; off >>= 1)
        local += __shfl_xor_sync(0xFFFFFFFFu, local, off);
    if (lid == 0) warp_sums[wid] = local;
    __syncthreads();
    if (tid == 0) {
        float sum = warp_sums[0] + warp_sums[1] + warp_sums[2] + warp_sums[3];
        atomicAdd(out, 0.5f * sum);
    }
}

__global__ void __launch_bounds__(256)
chamfer_final_kernel(float* __restrict__ out) {
    __shared__ float wsums[8];
    int idx = blockIdx.x * 256 + threadIdx.x;   // over BATCHES*NPTS = 131072
    int b = idx >> 10;
    int c = idx & (NPTS - 1);
    const int* part = g_colmin_part + (b * CHUNKS) * NPTS + c;
    int m = min(min(part[0],        part[NPTS]),
                min(part[2 * NPTS], part[3 * NPTS]));
    float v = __int_as_float(m) - 1.0f;
    float local = sqrtf(fmaxf(v, 0.0f) + 1e-16f);

    #pragma unroll
    for (int off = 16; off > 0; off >>= 1)
        local += __shfl_xor_sync(0xFFFFFFFFu, local, off);
    int wid = threadIdx.x >> 5, lid = threadIdx.x & 31;
    if (lid == 0) wsums[wid] = local;
    __syncthreads();
    if (wid == 0) {
        float s = (lid < 8) ? wsums[lid] : 0.0f;
        #pragma unroll
        for (int off = 4; off > 0; off >>= 1)
            s += __shfl_xor_sync(0xFFFFFFFFu, s, off);
        if (lid == 0) atomicAdd(out, 0.5f * s);
    }
}

extern "C" void kernel_launch(void* const* d_in, const int* in_sizes, int n_in,
                              void* d_out, int out_size) {
    const float4* p = (const float4*)d_in[0];
    const float4* q = (const float4*)d_in[1];
    float* out = (float*)d_out;

    chamfer_zero_kernel<<<1, 1>>>(out);
    chamfer_main_kernel<<<MAINGRID, THREADS>>>(p, q, out);
    chamfer_final_kernel<<<(BATCHES * NPTS) / 256, 256>>>(out);
}

// round 10
// speedup vs baseline: 1.2788x; 1.0787x over previous
#include <cuda_runtime.h>
#include <cuda_bf16.h>
#include <cstdint>

// ChamferLoss: B=128, N=M=1024, 3D points (float4, channel 0 unused).
// Single-pass, 2D-tiled: block = (batch, rowchunk<4, colchunk<2) covering
// 256 rows x 512 cols. Each distance computed ONCE feeds BOTH directions:
// row-min in registers (partial over 512 cols), col-min via one
// redux.sync.min.s32 per column (positive float bits are int-ordered).
// Both partial mins stored with plain STG; final kernel resolves and sums.
// Grid = 1024 blocks -> ~6.9 warps/SMSP for latency hiding.
// dist_sq+1 = (pn + (qn+1)) - 2*dot via packed f32x2.

#define BATCHES   128
#define NPTS      1024
#define THREADS   128
#define RPT       2
#define ROWS_PER_BLOCK (THREADS * RPT)        // 256
#define ROWCHUNKS (NPTS / ROWS_PER_BLOCK)     // 4
#define COLCHUNKS 2
#define COLS_PER_BLOCK (NPTS / COLCHUNKS)     // 512
#define NGROUPS_B (COLS_PER_BLOCK / 2)        // 256 packed column pairs
#define MAINGRID  (BATCHES * ROWCHUNKS * COLCHUNKS)   // 1024

__device__ int g_colmin_part[BATCHES * ROWCHUNKS * NPTS];  // [b][rowchunk][col]
__device__ int g_rowmin_part[BATCHES * COLCHUNKS * NPTS];  // [b][colchunk][row]

__device__ __forceinline__ unsigned long long pack2(float a, float b) {
    unsigned long long r;
    asm("mov.b64 %0, {%1, %2};" : "=l"(r) : "f"(a), "f"(b));
    return r;
}
__device__ __forceinline__ void unpack2(unsigned long long v, float& a, float& b) {
    asm("mov.b64 {%0, %1}, %2;" : "=f"(a), "=f"(b) : "l"(v));
}
__device__ __forceinline__ unsigned long long add2(unsigned long long a, unsigned long long b) {
    unsigned long long d;
    asm("add.rn.f32x2 %0, %1, %2;" : "=l"(d) : "l"(a), "l"(b));
    return d;
}
__device__ __forceinline__ unsigned long long fma2(unsigned long long a, unsigned long long b,
                                                   unsigned long long c) {
    unsigned long long d;
    asm("fma.rn.f32x2 %0, %1, %2, %3;" : "=l"(d) : "l"(a), "l"(b), "l"(c));
    return d;
}

__global__ void chamfer_zero_kernel(float* out) {
    out[0] = 0.0f;
}

__global__ void __launch_bounds__(THREADS)
chamfer_main_kernel(const float4* __restrict__ p, const float4* __restrict__ q) {
    // Packed column data: group j = q-points (base+2j, base+2j+1):
    //   sq[4j+0]=(y0,y1) sq[4j+1]=(z0,z1) sq[4j+2]=(w0,w1) sq[4j+3]=(qn0+1,qn1+1)
    __shared__ unsigned long long sq[(NGROUPS_B + 1) * 4];
    __shared__ int colmin_w[4 * COLS_PER_BLOCK];   // per-warp col-min bits

    const int bid      = blockIdx.x;
    const int colchunk = bid & (COLCHUNKS - 1);
    const int rowchunk = (bid >> 1) & (ROWCHUNKS - 1);
    const int b        = bid >> 3;
    const int tid      = threadIdx.x;
    const int wid      = tid >> 5;
    const int lid      = tid & 31;

    const float4* rowpts = p + b * NPTS;
    const float4* colpts = q + b * NPTS + colchunk * COLS_PER_BLOCK;

    // ---- Fill packed column smem (qn pre-biased by +1) ----
    #pragma unroll
    for (int i = tid; i < NGROUPS_B; i += THREADS) {
        float4 P0 = colpts[2 * i];
        float4 P1 = colpts[2 * i + 1];
        float n0 = P0.y * P0.y + P0.z * P0.z + P0.w * P0.w + 1.0f;
        float n1 = P1.y * P1.y + P1.z * P1.z + P1.w * P1.w + 1.0f;
        sq[4 * i + 0] = pack2(P0.y, P1.y);
        sq[4 * i + 1] = pack2(P0.z, P1.z);
        sq[4 * i + 2] = pack2(P0.w, P1.w);
        sq[4 * i + 3] = pack2(n0, n1);
    }
    if (tid < 4) sq[4 * NGROUPS_B + tid] = 0;   // prefetch padding

    // ---- This thread's 2 p-rows, coords pre-scaled by -2, pn pre-packed ----
    unsigned long long cx[RPT], cy[RPT], cz[RPT], pn2[RPT];
    #pragma unroll
    for (int k = 0; k < RPT; k++) {
        int r = rowchunk * ROWS_PER_BLOCK + k * THREADS + tid;
        float4 RP = rowpts[r];
        float pnk = RP.y * RP.y + RP.z * RP.z + RP.w * RP.w;
        cx[k] = pack2(-2.0f * RP.y, -2.0f * RP.y);
        cy[k] = pack2(-2.0f * RP.z, -2.0f * RP.z);
        cz[k] = pack2(-2.0f * RP.w, -2.0f * RP.w);
        pn2[k] = pack2(pnk, pnk);
    }

    __syncthreads();

    float rma[RPT], rmb[RPT];
    #pragma unroll
    for (int k = 0; k < RPT; k++) { rma[k] = 3.4e38f; rmb[k] = 3.4e38f; }

    const ulonglong2* sq2 = (const ulonglong2*)sq;
    int* cw = colmin_w + wid * COLS_PER_BLOCK;

    ulonglong2 u01 = sq2[0];
    ulonglong2 u23 = sq2[1];

    #pragma unroll 8
    for (int j = 0; j < NGROUPS_B; j++) {
        ulonglong2 n01 = sq2[2 * (j + 1)];
        ulonglong2 n23 = sq2[2 * (j + 1) + 1];

        float t0[RPT], t1[RPT];
        #pragma unroll
        for (int k = 0; k < RPT; k++) {
            // s = (pn + qn + 1) - 2*dot  -> strictly positive
            unsigned long long s = add2(u23.y, pn2[k]);
            s = fma2(cx[k], u01.x, s);
            s = fma2(cy[k], u01.y, s);
            s = fma2(cz[k], u23.x, s);
            unpack2(s, t0[k], t1[k]);
            rma[k] = fminf(rma[k], t0[k]);     // row-min partials
            rmb[k] = fminf(rmb[k], t1[k]);
        }

        // col-min: min over this lane's 2 rows, then across 32 lanes (64 rows)
        float c0f = fminf(t0[0], t0[1]);
        float c1f = fminf(t1[0], t1[1]);
        int c0 = __reduce_min_sync(0xFFFFFFFFu, __float_as_int(c0f));
        int c1 = __reduce_min_sync(0xFFFFFFFFu, __float_as_int(c1f));
        if (lid == 0) *(int2*)&cw[2 * j] = make_int2(c0, c1);

        u01 = n01;
        u23 = n23;
    }

    __syncthreads();

    // ---- Col-min: combine 4 warps, plain store to per-(b,rowchunk) partials ----
    int* gcol = g_colmin_part + (b * ROWCHUNKS + rowchunk) * NPTS
                              + colchunk * COLS_PER_BLOCK;
    #pragma unroll
    for (int c = tid; c < COLS_PER_BLOCK; c += THREADS) {
        int m = min(min(colmin_w[c],                      colmin_w[COLS_PER_BLOCK + c]),
                    min(colmin_w[2 * COLS_PER_BLOCK + c], colmin_w[3 * COLS_PER_BLOCK + c]));
        gcol[c] = m;
    }

    // ---- Row-min partials: plain store per (b, colchunk) ----
    int* grow = g_rowmin_part + (b * COLCHUNKS + colchunk) * NPTS
                              + rowchunk * ROWS_PER_BLOCK;
    #pragma unroll
    for (int k = 0; k < RPT; k++) {
        float rm = fminf(rma[k], rmb[k]);
        grow[k * THREADS + tid] = __float_as_int(rm);
    }
}

__global__ void __launch_bounds__(256)
chamfer_final_kernel(float* __restrict__ out) {
    __shared__ float wsums[8];
    int idx = blockIdx.x * 256 + threadIdx.x;   // over BATCHES*NPTS = 131072
    int b = idx >> 10;
    int i = idx & (NPTS - 1);

    // p-side: min over 2 colchunk partials for row i of batch b
    const int* rp = g_rowmin_part + b * COLCHUNKS * NPTS + i;
    int mr = min(rp[0], rp[NPTS]);
    float dr = __int_as_float(mr) - 1.0f;

    // q-side: min over 4 rowchunk partials for col i of batch b
    const int* cp = g_colmin_part + b * ROWCHUNKS * NPTS + i;
    int mc = min(min(cp[0],        cp[NPTS]),
                 min(cp[2 * NPTS], cp[3 * NPTS]));
    float dc = __int_as_float(mc) - 1.0f;

    float local = sqrtf(fmaxf(dr, 0.0f) + 1e-16f)
                + sqrtf(fmaxf(dc, 0.0f) + 1e-16f);

    #pragma unroll
    for (int off = 16; off > 0; off >>= 1)
        local += __shfl_xor_sync(0xFFFFFFFFu, local, off);
    int wid = threadIdx.x >> 5, lid = threadIdx.x & 31;
    if (lid == 0) wsums[wid] = local;
    __syncthreads();
    if (wid == 0) {
        float s = (lid < 8) ? wsums[lid] : 0.0f;
        #pragma unroll
        for (int off = 4; off > 0; off >>= 1)
            s += __shfl_xor_sync(0xFFFFFFFFu, s, off);
        if (lid == 0) atomicAdd(out, 0.5f * s);
    }
}

extern "C" void kernel_launch(void* const* d_in, const int* in_sizes, int n_in,
                              void* d_out, int out_size) {
    const float4* p = (const float4*)d_in[0];
    const float4* q = (const float4*)d_in[1];
    float* out = (float*)d_out;

    chamfer_zero_kernel<<<1, 1>>>(out);
    chamfer_main_kernel<<<MAINGRID, THREADS>>>(p, q);
    chamfer_final_kernel<<<(BATCHES * NPTS) / 256, 256>>>(out);
}

// round 11
// speedup vs baseline: 1.5163x; 1.1857x over previous
#include <cuda_runtime.h>
#include <cuda_bf16.h>
#include <cstdint>

// ChamferLoss: B=128, N=M=1024, 3D points (float4, channel 0 unused).
// Single-pass, 2D-tiled: block = (batch, rowchunk<2, colchunk<4) covering
// 512 rows x 256 cols (RPT=4 rows/thread). Each distance computed ONCE feeds
// BOTH directions: row-min in registers, col-min via one redux.sync.min.s32
// per column (positive float bits are int-ordered). Partial mins stored with
// plain STG; final kernel resolves both directions and sums.
// dist_sq+1 = (pn + (qn+1)) - 2*dot via packed f32x2. Grid = 1024 blocks.

#define BATCHES   128
#define NPTS      1024
#define THREADS   128
#define RPT       4
#define ROWS_PER_BLOCK (THREADS * RPT)        // 512
#define ROWCHUNKS (NPTS / ROWS_PER_BLOCK)     // 2
#define COLCHUNKS 4
#define COLS_PER_BLOCK (NPTS / COLCHUNKS)     // 256
#define NGROUPS_B (COLS_PER_BLOCK / 2)        // 128 packed column pairs
#define MAINGRID  (BATCHES * ROWCHUNKS * COLCHUNKS)   // 1024

__device__ int g_colmin_part[BATCHES * ROWCHUNKS * NPTS];  // [b][rowchunk][col]
__device__ int g_rowmin_part[BATCHES * COLCHUNKS * NPTS];  // [b][colchunk][row]

__device__ __forceinline__ unsigned long long pack2(float a, float b) {
    unsigned long long r;
    asm("mov.b64 %0, {%1, %2};" : "=l"(r) : "f"(a), "f"(b));
    return r;
}
__device__ __forceinline__ void unpack2(unsigned long long v, float& a, float& b) {
    asm("mov.b64 {%0, %1}, %2;" : "=f"(a), "=f"(b) : "l"(v));
}
__device__ __forceinline__ unsigned long long add2(unsigned long long a, unsigned long long b) {
    unsigned long long d;
    asm("add.rn.f32x2 %0, %1, %2;" : "=l"(d) : "l"(a), "l"(b));
    return d;
}
__device__ __forceinline__ unsigned long long fma2(unsigned long long a, unsigned long long b,
                                                   unsigned long long c) {
    unsigned long long d;
    asm("fma.rn.f32x2 %0, %1, %2, %3;" : "=l"(d) : "l"(a), "l"(b), "l"(c));
    return d;
}

__global__ void __launch_bounds__(THREADS)
chamfer_main_kernel(const float4* __restrict__ p, const float4* __restrict__ q,
                    float* __restrict__ out) {
    // Packed column data: group j = q-points (base+2j, base+2j+1):
    //   sq[4j+0]=(y0,y1) sq[4j+1]=(z0,z1) sq[4j+2]=(w0,w1) sq[4j+3]=(qn0+1,qn1+1)
    __shared__ unsigned long long sq[(NGROUPS_B + 1) * 4];
    __shared__ int colmin_w[4 * COLS_PER_BLOCK];   // per-warp col-min bits

    const int bid      = blockIdx.x;
    const int colchunk = bid & (COLCHUNKS - 1);
    const int rowchunk = (bid >> 2) & (ROWCHUNKS - 1);
    const int b        = bid >> 3;
    const int tid      = threadIdx.x;
    const int wid      = tid >> 5;
    const int lid      = tid & 31;

    if (bid == 0 && tid == 0) out[0] = 0.0f;   // stream-ordered before final

    const float4* rowpts = p + b * NPTS;
    const float4* colpts = q + b * NPTS + colchunk * COLS_PER_BLOCK;

    // ---- Fill packed column smem (qn pre-biased by +1) ----
    #pragma unroll
    for (int i = tid; i < NGROUPS_B; i += THREADS) {
        float4 P0 = colpts[2 * i];
        float4 P1 = colpts[2 * i + 1];
        float n0 = P0.y * P0.y + P0.z * P0.z + P0.w * P0.w + 1.0f;
        float n1 = P1.y * P1.y + P1.z * P1.z + P1.w * P1.w + 1.0f;
        sq[4 * i + 0] = pack2(P0.y, P1.y);
        sq[4 * i + 1] = pack2(P0.z, P1.z);
        sq[4 * i + 2] = pack2(P0.w, P1.w);
        sq[4 * i + 3] = pack2(n0, n1);
    }
    if (tid < 4) sq[4 * NGROUPS_B + tid] = 0;   // prefetch padding

    // ---- This thread's RPT p-rows, coords pre-scaled by -2, pn pre-packed ----
    unsigned long long cx[RPT], cy[RPT], cz[RPT], pn2[RPT];
    #pragma unroll
    for (int k = 0; k < RPT; k++) {
        int r = rowchunk * ROWS_PER_BLOCK + k * THREADS + tid;
        float4 RP = rowpts[r];
        float pnk = RP.y * RP.y + RP.z * RP.z + RP.w * RP.w;
        cx[k] = pack2(-2.0f * RP.y, -2.0f * RP.y);
        cy[k] = pack2(-2.0f * RP.z, -2.0f * RP.z);
        cz[k] = pack2(-2.0f * RP.w, -2.0f * RP.w);
        pn2[k] = pack2(pnk, pnk);
    }

    __syncthreads();

    float rma[RPT], rmb[RPT];
    #pragma unroll
    for (int k = 0; k < RPT; k++) { rma[k] = 3.4e38f; rmb[k] = 3.4e38f; }

    const ulonglong2* sq2 = (const ulonglong2*)sq;
    int* cw = colmin_w + wid * COLS_PER_BLOCK;

    ulonglong2 u01 = sq2[0];
    ulonglong2 u23 = sq2[1];

    #pragma unroll 4
    for (int j = 0; j < NGROUPS_B; j++) {
        ulonglong2 n01 = sq2[2 * (j + 1)];
        ulonglong2 n23 = sq2[2 * (j + 1) + 1];

        float t0[RPT], t1[RPT];
        #pragma unroll
        for (int k = 0; k < RPT; k++) {
            // s = (pn + qn + 1) - 2*dot  -> strictly positive
            unsigned long long s = add2(u23.y, pn2[k]);
            s = fma2(cx[k], u01.x, s);
            s = fma2(cy[k], u01.y, s);
            s = fma2(cz[k], u23.x, s);
            unpack2(s, t0[k], t1[k]);
            rma[k] = fminf(rma[k], t0[k]);     // row-min partials
            rmb[k] = fminf(rmb[k], t1[k]);
        }

        // col-min: 2-level tree over this lane's 4 rows, then across 32 lanes
        float c0f = fminf(fminf(t0[0], t0[1]), fminf(t0[2], t0[3]));
        float c1f = fminf(fminf(t1[0], t1[1]), fminf(t1[2], t1[3]));
        int c0 = __reduce_min_sync(0xFFFFFFFFu, __float_as_int(c0f));
        int c1 = __reduce_min_sync(0xFFFFFFFFu, __float_as_int(c1f));
        if (lid == 0) *(int2*)&cw[2 * j] = make_int2(c0, c1);

        u01 = n01;
        u23 = n23;
    }

    __syncthreads();

    // ---- Col-min: combine 4 warps, plain store to per-(b,rowchunk) partials ----
    int* gcol = g_colmin_part + (b * ROWCHUNKS + rowchunk) * NPTS
                              + colchunk * COLS_PER_BLOCK;
    #pragma unroll
    for (int c = tid; c < COLS_PER_BLOCK; c += THREADS) {
        int m = min(min(colmin_w[c],                      colmin_w[COLS_PER_BLOCK + c]),
                    min(colmin_w[2 * COLS_PER_BLOCK + c], colmin_w[3 * COLS_PER_BLOCK + c]));
        gcol[c] = m;
    }

    // ---- Row-min partials: plain store per (b, colchunk) ----
    int* grow = g_rowmin_part + (b * COLCHUNKS + colchunk) * NPTS
                              + rowchunk * ROWS_PER_BLOCK;
    #pragma unroll
    for (int k = 0; k < RPT; k++) {
        float rm = fminf(rma[k], rmb[k]);
        grow[k * THREADS + tid] = __float_as_int(rm);
    }
}

__global__ void __launch_bounds__(256)
chamfer_final_kernel(float* __restrict__ out) {
    __shared__ float wsums[8];
    int idx = blockIdx.x * 256 + threadIdx.x;   // over BATCHES*NPTS = 131072
    int b = idx >> 10;
    int i = idx & (NPTS - 1);

    // p-side: min over COLCHUNKS=4 colchunk partials for row i of batch b
    const int* rp = g_rowmin_part + b * COLCHUNKS * NPTS + i;
    int mr = min(min(rp[0],        rp[NPTS]),
                 min(rp[2 * NPTS], rp[3 * NPTS]));
    float dr = __int_as_float(mr) - 1.0f;

    // q-side: min over ROWCHUNKS=2 rowchunk partials for col i of batch b
    const int* cp = g_colmin_part + b * ROWCHUNKS * NPTS + i;
    int mc = min(cp[0], cp[NPTS]);
    float dc = __int_as_float(mc) - 1.0f;

    float local = sqrtf(fmaxf(dr, 0.0f) + 1e-16f)
                + sqrtf(fmaxf(dc, 0.0f) + 1e-16f);

    #pragma unroll
    for (int off = 16; off > 0; off >>= 1)
        local += __shfl_xor_sync(0xFFFFFFFFu, local, off);
    int wid = threadIdx.x >> 5, lid = threadIdx.x & 31;
    if (lid == 0) wsums[wid] = local;
    __syncthreads();
    if (wid == 0) {
        float s = (lid < 8) ? wsums[lid] : 0.0f;
        #pragma unroll
        for (int off = 4; off > 0; off >>= 1)
            s += __shfl_xor_sync(0xFFFFFFFFu, s, off);
        if (lid == 0) atomicAdd(out, 0.5f * s);
    }
}

extern "C" void kernel_launch(void* const* d_in, const int* in_sizes, int n_in,
                              void* d_out, int out_size) {
    const float4* p = (const float4*)d_in[0];
    const float4* q = (const float4*)d_in[1];
    float* out = (float*)d_out;

    chamfer_main_kernel<<<MAINGRID, THREADS>>>(p, q, out);
    chamfer_final_kernel<<<(BATCHES * NPTS) / 256, 256>>>(out);
}